// round 2
// baseline (speedup 1.0000x reference)
#include <cuda_runtime.h>
#include <math.h>

#define N_NODES   100000
#define E_EDGES   3200000
#define F_INF     128
#define HC        128
#define H_HEADS   4
#define C_CH      32
#define G_GRAPHS  64
#define NCLS      10
#define NEG_SLOPE 0.2f

// ---------------- scratch (device globals; no allocation allowed) ----------
__device__ __align__(16) float g_h[(size_t)N_NODES * HC];        // 51.2 MB
__device__ __align__(16) float g_out[(size_t)N_NODES * HC];      // 51.2 MB
__device__ __align__(16) float g_asrc[N_NODES * H_HEADS];        // 1.6 MB
__device__ __align__(16) float g_adst[N_NODES * H_HEADS];        // 1.6 MB
__device__ __align__(16) float g_denom[N_NODES * H_HEADS];       // 1.6 MB
__device__ __align__(16) float g_pool[G_GRAPHS * HC];            // 32 KB

// vectorized reduction (no return) — 4x fewer LTS atomic ops than scalar
__device__ __forceinline__ void red_add_v4(float* addr, float a, float b, float c, float d) {
    asm volatile("red.global.add.v4.f32 [%0], {%1,%2,%3,%4};"
                 :: "l"(__cvta_generic_to_global(addr)),
                    "f"(a), "f"(b), "f"(c), "f"(d)
                 : "memory");
}

// ---------------- kernel 0: zero the accumulated scratch -------------------
__global__ void zero_scratch() {
    int i = blockIdx.x * blockDim.x + threadIdx.x;
    float4 z = make_float4(0.f, 0.f, 0.f, 0.f);
    const int nOut4 = N_NODES * HC / 4;          // 3.2M
    if (i < nOut4)            ((float4*)g_out)[i]   = z;
    if (i < N_NODES)          ((float4*)g_denom)[i] = z;   // N*4 floats = N float4
    if (i < G_GRAPHS * HC/4)  ((float4*)g_pool)[i]  = z;
}

// ---------------- kernel 1: SGEMM h = x@W with fused attention projections -
// Block: 256 threads, tile 64 rows x 128 cols, K looped in chunks of 32.
// Epilogue: a_src[n,h] = sum_c h[n,h,c]*att_src[h,c] via 8-lane shuffles.
__global__ void gemm_gat(const float* __restrict__ x, const float* __restrict__ W,
                         const float* __restrict__ att_src, const float* __restrict__ att_dst) {
    __shared__ __align__(16) float xs[64][33];
    __shared__ __align__(16) float ws[32][132];   // 132*4=528B row pitch, 16B multiple
    __shared__ __align__(16) float att_s[2][HC];

    const int tid  = threadIdx.x;
    const int lane = tid & 31;
    const int warp = tid >> 5;             // 0..7: owns rows warp*8 .. warp*8+7
    const int row0 = blockIdx.x * 64;

    if (tid < HC) { att_s[0][tid] = att_src[tid]; att_s[1][tid] = att_dst[tid]; }

    float acc[8][4];
#pragma unroll
    for (int r = 0; r < 8; ++r)
#pragma unroll
        for (int c = 0; c < 4; ++c) acc[r][c] = 0.f;

    for (int kc = 0; kc < 4; ++kc) {
        // load x tile (64x32) as float4
#pragma unroll
        for (int i = 0; i < 2; ++i) {
            int idx = tid + i * 256;       // 0..511 float4 slots, 8 per row
            int r = idx >> 3, c4 = idx & 7;
            float4 v = make_float4(0.f, 0.f, 0.f, 0.f);
            if (row0 + r < N_NODES)
                v = *(const float4*)&x[(size_t)(row0 + r) * F_INF + kc * 32 + c4 * 4];
            xs[r][c4 * 4 + 0] = v.x; xs[r][c4 * 4 + 1] = v.y;
            xs[r][c4 * 4 + 2] = v.z; xs[r][c4 * 4 + 3] = v.w;
        }
        // load W tile (32x128) as float4
#pragma unroll
        for (int i = 0; i < 4; ++i) {
            int idx = tid + i * 256;       // 0..1023 float4 slots, 32 per row
            int r = idx >> 5, c4 = idx & 31;
            float4 v = *(const float4*)&W[(size_t)(kc * 32 + r) * HC + c4 * 4];
            *(float4*)&ws[r][c4 * 4] = v;
        }
        __syncthreads();

#pragma unroll
        for (int k = 0; k < 32; ++k) {
            float xv[8];
#pragma unroll
            for (int r = 0; r < 8; ++r) xv[r] = xs[warp * 8 + r][k];
            float4 wv = *(float4*)&ws[k][lane * 4];
#pragma unroll
            for (int r = 0; r < 8; ++r) {
                acc[r][0] += xv[r] * wv.x;
                acc[r][1] += xv[r] * wv.y;
                acc[r][2] += xv[r] * wv.z;
                acc[r][3] += xv[r] * wv.w;
            }
        }
        __syncthreads();
    }

    // epilogue: store h, compute a_src / a_dst
    const int head = lane >> 3;            // cols lane*4.. are inside head lane/8
    const int cbase = (lane & 7) * 4;      // within-head channel base
#pragma unroll
    for (int r = 0; r < 8; ++r) {
        int row = row0 + warp * 8 + r;     // uniform across the warp
        if (row < N_NODES) {
            float4 hv = make_float4(acc[r][0], acc[r][1], acc[r][2], acc[r][3]);
            *(float4*)&g_h[(size_t)row * HC + lane * 4] = hv;
            float ps = 0.f, pd = 0.f;
#pragma unroll
            for (int c = 0; c < 4; ++c) {
                ps += acc[r][c] * att_s[0][head * C_CH + cbase + c];
                pd += acc[r][c] * att_s[1][head * C_CH + cbase + c];
            }
#pragma unroll
            for (int o = 1; o < 8; o <<= 1) {
                ps += __shfl_xor_sync(0xffffffffu, ps, o);
                pd += __shfl_xor_sync(0xffffffffu, pd, o);
            }
            if ((lane & 7) == 0) {
                g_asrc[row * H_HEADS + head] = ps;
                g_adst[row * H_HEADS + head] = pd;
            }
        }
    }
}

// ---------------- kernel 2: edge pass A — softmax denominators -------------
// (max-pass eliminated: e ~ N(0,2); exp(e) can't overflow fp32, and
//  exp(e)/sum(exp(e)) == softmax exactly in real arithmetic)
__global__ void edge_denom(const int* __restrict__ src,
                           const int* __restrict__ dst) {
    int i = blockIdx.x * blockDim.x + threadIdx.x;
    if (i >= E_EDGES) return;
    int s = src[i], d = dst[i];
    float4 as = ((const float4*)g_asrc)[s];
    float4 ad = ((const float4*)g_adst)[d];
    float e0 = as.x + ad.x; e0 = e0 > 0.f ? e0 : NEG_SLOPE * e0;
    float e1 = as.y + ad.y; e1 = e1 > 0.f ? e1 : NEG_SLOPE * e1;
    float e2 = as.z + ad.z; e2 = e2 > 0.f ? e2 : NEG_SLOPE * e2;
    float e3 = as.w + ad.w; e3 = e3 > 0.f ? e3 : NEG_SLOPE * e3;
    red_add_v4(&g_denom[d * H_HEADS], __expf(e0), __expf(e1), __expf(e2), __expf(e3));
}

// ---------------- kernel 3: edge pass B — weighted scatter (warp per edge) -
__global__ void edge_scatter(const int* __restrict__ src,
                             const int* __restrict__ dst) {
    int e = (blockIdx.x * blockDim.x + threadIdx.x) >> 5;
    int lane = threadIdx.x & 31;
    if (e >= E_EDGES) return;
    int s = src[e], d = dst[e];                 // same addr all lanes -> broadcast
    int head = lane >> 3;
    float ev = g_asrc[s * H_HEADS + head] + g_adst[d * H_HEADS + head];
    ev = ev > 0.f ? ev : NEG_SLOPE * ev;
    float alpha = __expf(ev) / (g_denom[d * H_HEADS + head] + 1e-16f);
    float4 hv = ((const float4*)g_h)[(size_t)s * (HC / 4) + lane];
    red_add_v4(&g_out[(size_t)d * HC + lane * 4],
               hv.x * alpha, hv.y * alpha, hv.z * alpha, hv.w * alpha);
}

// ---------------- kernel 4: fused bias+ELU+mean-pool partials --------------
#define NODES_PER_BLOCK 512
__global__ void pool_kernel(const int* __restrict__ batch,
                            const float* __restrict__ conv_bias) {
    int t = threadIdx.x;                        // channel, 128 threads
    int n0 = blockIdx.x * NODES_PER_BLOCK;
    if (n0 >= N_NODES) return;
    int n1 = min(n0 + NODES_PER_BLOCK, N_NODES);
    float bias = conv_bias[t];
    int cur = batch[n0];
    float acc = 0.f;
    for (int n = n0; n < n1; ++n) {
        int g = batch[n];
        if (g != cur) {
            atomicAdd(&g_pool[cur * HC + t], acc);
            acc = 0.f; cur = g;
        }
        float v = g_out[(size_t)n * HC + t] + bias;
        v = v > 0.f ? v : (__expf(v) - 1.0f);   // ELU
        acc += v;
    }
    atomicAdd(&g_pool[cur * HC + t], acc);
}

// ---------------- kernel 5: classifier + log_softmax -----------------------
__global__ void classify(const int* __restrict__ batch,
                         const float* __restrict__ lin_w,
                         const float* __restrict__ lin_b,
                         float* __restrict__ out) {
    int g = blockIdx.x, t = threadIdx.x;        // 128 threads per graph
    __shared__ float p[HC];
    __shared__ float logits[NCLS];
    __shared__ int s_cnt;
    if (t == 0) {
        int lo = 0, hi = N_NODES;
        while (lo < hi) { int mid = (lo + hi) >> 1; if (batch[mid] <  g) lo = mid + 1; else hi = mid; }
        int lb = lo;
        lo = lb; hi = N_NODES;
        while (lo < hi) { int mid = (lo + hi) >> 1; if (batch[mid] <= g) lo = mid + 1; else hi = mid; }
        s_cnt = lo - lb;
    }
    __syncthreads();
    float cnt = fmaxf((float)s_cnt, 1.0f);
    p[t] = g_pool[g * HC + t] / cnt;
    __syncthreads();
    if (t < NCLS) {
        float acc = lin_b[t];
#pragma unroll 16
        for (int c = 0; c < HC; ++c) acc += p[c] * lin_w[c * NCLS + t];
        logits[t] = acc;
    }
    __syncthreads();
    if (t < NCLS) {
        float m = logits[0];
#pragma unroll
        for (int j = 1; j < NCLS; ++j) m = fmaxf(m, logits[j]);
        float ssum = 0.f;
#pragma unroll
        for (int j = 0; j < NCLS; ++j) ssum += __expf(logits[j] - m);
        out[g * NCLS + t] = logits[t] - m - logf(ssum);
    }
}

// ---------------- launch ----------------------------------------------------
extern "C" void kernel_launch(void* const* d_in, const int* in_sizes, int n_in,
                              void* d_out, int out_size) {
    const float* x        = (const float*)d_in[0];
    const int*   ei       = (const int*)d_in[1];     // int32! (JAX truncates int64)
    const int*   batch    = (const int*)d_in[2];     // int32!
    const float* W        = (const float*)d_in[3];
    const float* att_src  = (const float*)d_in[4];
    const float* att_dst  = (const float*)d_in[5];
    const float* conv_b   = (const float*)d_in[6];
    const float* lin_w    = (const float*)d_in[7];
    const float* lin_b    = (const float*)d_in[8];
    float*       out      = (float*)d_out;

    const int* src = ei;
    const int* dst = ei + E_EDGES;

    const int nZero = N_NODES * HC / 4;                 // 3.2M threads
    zero_scratch<<<(nZero + 255) / 256, 256>>>();
    gemm_gat<<<(N_NODES + 63) / 64, 256>>>(x, W, att_src, att_dst);
    edge_denom<<<(E_EDGES + 255) / 256, 256>>>(src, dst);
    edge_scatter<<<(E_EDGES * 32 + 255) / 256, 256>>>(src, dst);
    pool_kernel<<<(N_NODES + NODES_PER_BLOCK - 1) / NODES_PER_BLOCK, 128>>>(batch, conv_b);
    classify<<<G_GRAPHS, 128>>>(batch, lin_w, lin_b, out);
}

// round 3
// speedup vs baseline: 1.7111x; 1.7111x over previous
#include <cuda_runtime.h>
#include <math.h>

#define N_NODES   100000
#define E_EDGES   3200000
#define F_INF     128
#define HC        128
#define H_HEADS   4
#define C_CH      32
#define G_GRAPHS  64
#define NCLS      10
#define NEG_SLOPE 0.2f

// ---------------- scratch (device globals; no allocation allowed) ----------
__device__ __align__(16) float  g_h[(size_t)N_NODES * HC];       // 51.2 MB
__device__ __align__(16) float2 g_eas[N_NODES * H_HEADS];        // (exp(a_src), exp(0.2 a_src))
__device__ __align__(16) float2 g_ead[N_NODES * H_HEADS];        // (exp(a_dst), exp(0.2 a_dst))
__device__ __align__(16) int    g_cnt[N_NODES];                  // histogram -> cursor
__device__ __align__(16) int    g_offs[N_NODES + 1];             // CSR offsets
__device__ __align__(16) int    g_csrc[E_EDGES];                 // src ids grouped by dst
__device__ __align__(16) float  g_pool[G_GRAPHS * HC];           // pooled sums

__device__ __forceinline__ void red_add_v4(float* addr, float a, float b, float c, float d) {
    asm volatile("red.global.add.v4.f32 [%0], {%1,%2,%3,%4};"
                 :: "l"(__cvta_generic_to_global(addr)),
                    "f"(a), "f"(b), "f"(c), "f"(d)
                 : "memory");
}

// ---------------- kernel 0: zero counters + pool ---------------------------
__global__ void zero_scratch() {
    int i = blockIdx.x * blockDim.x + threadIdx.x;
    if (i < N_NODES / 4)         ((int4*)g_cnt)[i] = make_int4(0, 0, 0, 0);
    if (i < G_GRAPHS * HC / 4)   ((float4*)g_pool)[i] = make_float4(0.f, 0.f, 0.f, 0.f);
}

// ---------------- kernel 1: SGEMM h = x@W + attention exp tables -----------
__global__ void gemm_gat(const float* __restrict__ x, const float* __restrict__ W,
                         const float* __restrict__ att_src, const float* __restrict__ att_dst) {
    __shared__ __align__(16) float xs[64][33];
    __shared__ __align__(16) float ws[32][132];
    __shared__ __align__(16) float att_s[2][HC];

    const int tid  = threadIdx.x;
    const int lane = tid & 31;
    const int warp = tid >> 5;
    const int row0 = blockIdx.x * 64;

    if (tid < HC) { att_s[0][tid] = att_src[tid]; att_s[1][tid] = att_dst[tid]; }

    float acc[8][4];
#pragma unroll
    for (int r = 0; r < 8; ++r)
#pragma unroll
        for (int c = 0; c < 4; ++c) acc[r][c] = 0.f;

    for (int kc = 0; kc < 4; ++kc) {
#pragma unroll
        for (int i = 0; i < 2; ++i) {
            int idx = tid + i * 256;
            int r = idx >> 3, c4 = idx & 7;
            float4 v = make_float4(0.f, 0.f, 0.f, 0.f);
            if (row0 + r < N_NODES)
                v = *(const float4*)&x[(size_t)(row0 + r) * F_INF + kc * 32 + c4 * 4];
            xs[r][c4 * 4 + 0] = v.x; xs[r][c4 * 4 + 1] = v.y;
            xs[r][c4 * 4 + 2] = v.z; xs[r][c4 * 4 + 3] = v.w;
        }
#pragma unroll
        for (int i = 0; i < 4; ++i) {
            int idx = tid + i * 256;
            int r = idx >> 5, c4 = idx & 31;
            float4 v = *(const float4*)&W[(size_t)(kc * 32 + r) * HC + c4 * 4];
            *(float4*)&ws[r][c4 * 4] = v;
        }
        __syncthreads();

#pragma unroll
        for (int k = 0; k < 32; ++k) {
            float xv[8];
#pragma unroll
            for (int r = 0; r < 8; ++r) xv[r] = xs[warp * 8 + r][k];
            float4 wv = *(float4*)&ws[k][lane * 4];
#pragma unroll
            for (int r = 0; r < 8; ++r) {
                acc[r][0] += xv[r] * wv.x;
                acc[r][1] += xv[r] * wv.y;
                acc[r][2] += xv[r] * wv.z;
                acc[r][3] += xv[r] * wv.w;
            }
        }
        __syncthreads();
    }

    const int head  = lane >> 3;
    const int cbase = (lane & 7) * 4;
#pragma unroll
    for (int r = 0; r < 8; ++r) {
        int row = row0 + warp * 8 + r;
        if (row < N_NODES) {
            *(float4*)&g_h[(size_t)row * HC + lane * 4] =
                make_float4(acc[r][0], acc[r][1], acc[r][2], acc[r][3]);
            float ps = 0.f, pd = 0.f;
#pragma unroll
            for (int c = 0; c < 4; ++c) {
                ps += acc[r][c] * att_s[0][head * C_CH + cbase + c];
                pd += acc[r][c] * att_s[1][head * C_CH + cbase + c];
            }
#pragma unroll
            for (int o = 1; o < 8; o <<= 1) {
                ps += __shfl_xor_sync(0xffffffffu, ps, o);
                pd += __shfl_xor_sync(0xffffffffu, pd, o);
            }
            if ((lane & 7) == 0) {
                g_eas[row * H_HEADS + head] = make_float2(__expf(ps), __expf(NEG_SLOPE * ps));
                g_ead[row * H_HEADS + head] = make_float2(__expf(pd), __expf(NEG_SLOPE * pd));
            }
        }
    }
}

// ---------------- kernel 2: histogram of dst -------------------------------
__global__ void hist_kernel(const int* __restrict__ dst) {
    int i = blockIdx.x * blockDim.x + threadIdx.x;
    if (i < E_EDGES / 4) {
        int4 d4 = ((const int4*)dst)[i];
        atomicAdd(&g_cnt[d4.x], 1);
        atomicAdd(&g_cnt[d4.y], 1);
        atomicAdd(&g_cnt[d4.z], 1);
        atomicAdd(&g_cnt[d4.w], 1);
    }
}

// ---------------- kernel 3: exclusive scan (single block) ------------------
__global__ void scan_kernel() {
    __shared__ int ssum[1024];
    const int tid = threadIdx.x;
    const int SEG = (N_NODES + 1023) / 1024;       // 98
    int s0 = tid * SEG, s1 = min(s0 + SEG, N_NODES);
    int sum = 0;
    for (int i = s0; i < s1; ++i) sum += g_cnt[i];
    ssum[tid] = sum;
    __syncthreads();
    for (int off = 1; off < 1024; off <<= 1) {
        int v = (tid >= off) ? ssum[tid - off] : 0;
        __syncthreads();
        ssum[tid] += v;
        __syncthreads();
    }
    int run = (tid == 0) ? 0 : ssum[tid - 1];
    for (int i = s0; i < s1; ++i) {
        int c = g_cnt[i];
        g_offs[i] = run;
        g_cnt[i]  = run;       // cursor for scatter
        run += c;
    }
    if (tid == 0) g_offs[N_NODES] = E_EDGES;
}

// ---------------- kernel 4: scatter src ids into CSR buckets ---------------
__global__ void csr_scatter(const int* __restrict__ src, const int* __restrict__ dst) {
    int i = blockIdx.x * blockDim.x + threadIdx.x;
    if (i >= E_EDGES) return;
    int d = dst[i];
    int p = atomicAdd(&g_cnt[d], 1);
    g_csrc[p] = src[i];
}

// ---------------- kernel 5: fused gather + softmax + bias + ELU + pool -----
// One warp per dst node. Accumulates sum(w*h[src]) and sum(w) in registers;
// single divide at the end (softmax denominator comes for free).
__global__ void gat_gather(const int* __restrict__ batch,
                           const float* __restrict__ conv_bias) {
    const int lane = threadIdx.x & 31;
    const int d = blockIdx.x * 8 + (threadIdx.x >> 5);
    if (d >= N_NODES) return;
    const int head = lane >> 3;

    const int o0 = g_offs[d], o1 = g_offs[d + 1];
    const float2 ead = g_ead[d * H_HEADS + head];

    float4 acc = make_float4(0.f, 0.f, 0.f, 0.f);
    float densum = 0.f;

    int base = o0;
    for (; base + 32 <= o1; base += 32) {
        int eid = g_csrc[base + lane];
#pragma unroll 8
        for (int j = 0; j < 32; ++j) {
            int s = __shfl_sync(0xffffffffu, eid, j);
            float2 ef = __ldg(&g_eas[s * H_HEADS + head]);
            float p = ef.x * ead.x;
            float w = (p > 1.f) ? p : ef.y * ead.y;
            float4 hv = __ldg(&((const float4*)g_h)[(size_t)s * (HC / 4) + lane]);
            acc.x += w * hv.x; acc.y += w * hv.y;
            acc.z += w * hv.z; acc.w += w * hv.w;
            densum += w;
        }
    }
    int rem = o1 - base;
    if (rem > 0) {
        int eid = (lane < rem) ? g_csrc[base + lane] : 0;
        for (int j = 0; j < rem; ++j) {
            int s = __shfl_sync(0xffffffffu, eid, j);
            float2 ef = __ldg(&g_eas[s * H_HEADS + head]);
            float p = ef.x * ead.x;
            float w = (p > 1.f) ? p : ef.y * ead.y;
            float4 hv = __ldg(&((const float4*)g_h)[(size_t)s * (HC / 4) + lane]);
            acc.x += w * hv.x; acc.y += w * hv.y;
            acc.z += w * hv.z; acc.w += w * hv.w;
            densum += w;
        }
    }

    float inv = (densum > 0.f) ? 1.f / densum : 0.f;   // deg==0 -> out = bias
    float4 bv = __ldg(&((const float4*)conv_bias)[lane]);
    float vx = acc.x * inv + bv.x; vx = vx > 0.f ? vx : __expf(vx) - 1.f;
    float vy = acc.y * inv + bv.y; vy = vy > 0.f ? vy : __expf(vy) - 1.f;
    float vz = acc.z * inv + bv.z; vz = vz > 0.f ? vz : __expf(vz) - 1.f;
    float vw = acc.w * inv + bv.w; vw = vw > 0.f ? vw : __expf(vw) - 1.f;

    int g = batch[d];
    red_add_v4(&g_pool[g * HC + lane * 4], vx, vy, vz, vw);
}

// ---------------- kernel 6: classifier + log_softmax -----------------------
__global__ void classify(const int* __restrict__ batch,
                         const float* __restrict__ lin_w,
                         const float* __restrict__ lin_b,
                         float* __restrict__ out) {
    int g = blockIdx.x, t = threadIdx.x;
    __shared__ float p[HC];
    __shared__ float logits[NCLS];
    __shared__ int s_cnt;
    if (t == 0) {
        int lo = 0, hi = N_NODES;
        while (lo < hi) { int mid = (lo + hi) >> 1; if (batch[mid] <  g) lo = mid + 1; else hi = mid; }
        int lb = lo;
        lo = lb; hi = N_NODES;
        while (lo < hi) { int mid = (lo + hi) >> 1; if (batch[mid] <= g) lo = mid + 1; else hi = mid; }
        s_cnt = lo - lb;
    }
    __syncthreads();
    float cnt = fmaxf((float)s_cnt, 1.0f);
    p[t] = g_pool[g * HC + t] / cnt;
    __syncthreads();
    if (t < NCLS) {
        float acc = lin_b[t];
#pragma unroll 16
        for (int c = 0; c < HC; ++c) acc += p[c] * lin_w[c * NCLS + t];
        logits[t] = acc;
    }
    __syncthreads();
    if (t < NCLS) {
        float m = logits[0];
#pragma unroll
        for (int j = 1; j < NCLS; ++j) m = fmaxf(m, logits[j]);
        float ssum = 0.f;
#pragma unroll
        for (int j = 0; j < NCLS; ++j) ssum += __expf(logits[j] - m);
        out[g * NCLS + t] = logits[t] - m - logf(ssum);
    }
}

// ---------------- launch ----------------------------------------------------
extern "C" void kernel_launch(void* const* d_in, const int* in_sizes, int n_in,
                              void* d_out, int out_size) {
    const float* x        = (const float*)d_in[0];
    const int*   ei       = (const int*)d_in[1];     // int32 (JAX truncates int64)
    const int*   batch    = (const int*)d_in[2];
    const float* W        = (const float*)d_in[3];
    const float* att_src  = (const float*)d_in[4];
    const float* att_dst  = (const float*)d_in[5];
    const float* conv_b   = (const float*)d_in[6];
    const float* lin_w    = (const float*)d_in[7];
    const float* lin_b    = (const float*)d_in[8];
    float*       out      = (float*)d_out;

    const int* src = ei;
    const int* dst = ei + E_EDGES;

    zero_scratch<<<(N_NODES / 4 + 255) / 256, 256>>>();
    gemm_gat<<<(N_NODES + 63) / 64, 256>>>(x, W, att_src, att_dst);
    hist_kernel<<<(E_EDGES / 4 + 255) / 256, 256>>>(dst);
    scan_kernel<<<1, 1024>>>();
    csr_scatter<<<(E_EDGES + 255) / 256, 256>>>(src, dst);
    gat_gather<<<(N_NODES + 7) / 8, 256>>>(batch, conv_b);
    classify<<<G_GRAPHS, 128>>>(batch, lin_w, lin_b, out);
}

// round 4
// speedup vs baseline: 2.3298x; 1.3615x over previous
#include <cuda_runtime.h>
#include <math.h>

#define N_NODES   100000
#define E_EDGES   3200000
#define F_INF     128
#define HC        128
#define H_HEADS   4
#define C_CH      32
#define G_GRAPHS  64
#define NCLS      10
#define NEG_SLOPE 0.2f

#define SCAN_BLK  256
#define NBLK      ((N_NODES + SCAN_BLK - 1) / SCAN_BLK)   // 391

// ---------------- scratch (device globals; no allocation allowed) ----------
__device__ __align__(16) float  g_h[(size_t)N_NODES * HC];       // 51.2 MB
__device__ __align__(16) float2 g_eas[N_NODES * H_HEADS];        // (exp(a_src), exp(0.2 a_src))
__device__ __align__(16) float2 g_ead[N_NODES * H_HEADS];        // (exp(a_dst), exp(0.2 a_dst))
__device__ __align__(16) int    g_cnt[N_NODES];                  // histogram -> cursor
__device__ __align__(16) int    g_offs[N_NODES + 1];             // CSR offsets
__device__ __align__(16) int    g_csrc[E_EDGES];                 // src ids grouped by dst
__device__ __align__(16) float  g_pool[G_GRAPHS * HC];           // pooled sums
__device__ __align__(16) int    g_bsum[NBLK];                    // per-block sums

__device__ __forceinline__ void red_add_v4(float* addr, float a, float b, float c, float d) {
    asm volatile("red.global.add.v4.f32 [%0], {%1,%2,%3,%4};"
                 :: "l"(__cvta_generic_to_global(addr)),
                    "f"(a), "f"(b), "f"(c), "f"(d)
                 : "memory");
}

// ---------------- kernel 0: zero counters + pool ---------------------------
__global__ void zero_scratch() {
    int i = blockIdx.x * blockDim.x + threadIdx.x;
    if (i < N_NODES / 4)         ((int4*)g_cnt)[i] = make_int4(0, 0, 0, 0);
    if (i < G_GRAPHS * HC / 4)   ((float4*)g_pool)[i] = make_float4(0.f, 0.f, 0.f, 0.f);
}

// ---------------- kernel 1: SGEMM h = x@W + attention exp tables -----------
__global__ void gemm_gat(const float* __restrict__ x, const float* __restrict__ W,
                         const float* __restrict__ att_src, const float* __restrict__ att_dst) {
    __shared__ __align__(16) float xs[64][33];
    __shared__ __align__(16) float ws[32][132];
    __shared__ __align__(16) float att_s[2][HC];

    const int tid  = threadIdx.x;
    const int lane = tid & 31;
    const int warp = tid >> 5;
    const int row0 = blockIdx.x * 64;

    if (tid < HC) { att_s[0][tid] = att_src[tid]; att_s[1][tid] = att_dst[tid]; }

    float acc[8][4];
#pragma unroll
    for (int r = 0; r < 8; ++r)
#pragma unroll
        for (int c = 0; c < 4; ++c) acc[r][c] = 0.f;

    for (int kc = 0; kc < 4; ++kc) {
#pragma unroll
        for (int i = 0; i < 2; ++i) {
            int idx = tid + i * 256;
            int r = idx >> 3, c4 = idx & 7;
            float4 v = make_float4(0.f, 0.f, 0.f, 0.f);
            if (row0 + r < N_NODES)
                v = *(const float4*)&x[(size_t)(row0 + r) * F_INF + kc * 32 + c4 * 4];
            xs[r][c4 * 4 + 0] = v.x; xs[r][c4 * 4 + 1] = v.y;
            xs[r][c4 * 4 + 2] = v.z; xs[r][c4 * 4 + 3] = v.w;
        }
#pragma unroll
        for (int i = 0; i < 4; ++i) {
            int idx = tid + i * 256;
            int r = idx >> 5, c4 = idx & 31;
            float4 v = *(const float4*)&W[(size_t)(kc * 32 + r) * HC + c4 * 4];
            *(float4*)&ws[r][c4 * 4] = v;
        }
        __syncthreads();

#pragma unroll
        for (int k = 0; k < 32; ++k) {
            float xv[8];
#pragma unroll
            for (int r = 0; r < 8; ++r) xv[r] = xs[warp * 8 + r][k];
            float4 wv = *(float4*)&ws[k][lane * 4];
#pragma unroll
            for (int r = 0; r < 8; ++r) {
                acc[r][0] += xv[r] * wv.x;
                acc[r][1] += xv[r] * wv.y;
                acc[r][2] += xv[r] * wv.z;
                acc[r][3] += xv[r] * wv.w;
            }
        }
        __syncthreads();
    }

    const int head  = lane >> 3;
    const int cbase = (lane & 7) * 4;
#pragma unroll
    for (int r = 0; r < 8; ++r) {
        int row = row0 + warp * 8 + r;
        if (row < N_NODES) {
            *(float4*)&g_h[(size_t)row * HC + lane * 4] =
                make_float4(acc[r][0], acc[r][1], acc[r][2], acc[r][3]);
            float ps = 0.f, pd = 0.f;
#pragma unroll
            for (int c = 0; c < 4; ++c) {
                ps += acc[r][c] * att_s[0][head * C_CH + cbase + c];
                pd += acc[r][c] * att_s[1][head * C_CH + cbase + c];
            }
#pragma unroll
            for (int o = 1; o < 8; o <<= 1) {
                ps += __shfl_xor_sync(0xffffffffu, ps, o);
                pd += __shfl_xor_sync(0xffffffffu, pd, o);
            }
            if ((lane & 7) == 0) {
                g_eas[row * H_HEADS + head] = make_float2(__expf(ps), __expf(NEG_SLOPE * ps));
                g_ead[row * H_HEADS + head] = make_float2(__expf(pd), __expf(NEG_SLOPE * pd));
            }
        }
    }
}

// ---------------- kernel 2: histogram of dst -------------------------------
__global__ void hist_kernel(const int* __restrict__ dst) {
    int i = blockIdx.x * blockDim.x + threadIdx.x;
    if (i < E_EDGES / 4) {
        int4 d4 = ((const int4*)dst)[i];
        atomicAdd(&g_cnt[d4.x], 1);
        atomicAdd(&g_cnt[d4.y], 1);
        atomicAdd(&g_cnt[d4.z], 1);
        atomicAdd(&g_cnt[d4.w], 1);
    }
}

// ---------------- kernel 3a: per-block sums of g_cnt -----------------------
__global__ void scan_blocksum() {
    __shared__ int warp_s[SCAN_BLK / 32];
    int i = blockIdx.x * SCAN_BLK + threadIdx.x;
    int v = (i < N_NODES) ? g_cnt[i] : 0;
#pragma unroll
    for (int o = 16; o > 0; o >>= 1) v += __shfl_xor_sync(0xffffffffu, v, o);
    if ((threadIdx.x & 31) == 0) warp_s[threadIdx.x >> 5] = v;
    __syncthreads();
    if (threadIdx.x == 0) {
        int s = 0;
#pragma unroll
        for (int w = 0; w < SCAN_BLK / 32; ++w) s += warp_s[w];
        g_bsum[blockIdx.x] = s;
    }
}

// ---------------- kernel 3b: exclusive scan over block sums (1 block) ------
__global__ void scan_tops() {
    __shared__ int s[512];
    int tid = threadIdx.x;
    s[tid] = (tid < NBLK) ? g_bsum[tid] : 0;
    __syncthreads();
#pragma unroll
    for (int off = 1; off < 512; off <<= 1) {
        int v = (tid >= off) ? s[tid - off] : 0;
        __syncthreads();
        s[tid] += v;
        __syncthreads();
    }
    if (tid < NBLK) g_bsum[tid] = (tid == 0) ? 0 : s[tid - 1];   // exclusive
}

// ---------------- kernel 3c: local scan + offset -> g_offs / cursor --------
__global__ void scan_finalize() {
    __shared__ int s[SCAN_BLK];
    int tid = threadIdx.x;
    int i = blockIdx.x * SCAN_BLK + tid;
    int c = (i < N_NODES) ? g_cnt[i] : 0;
    s[tid] = c;
    __syncthreads();
#pragma unroll
    for (int off = 1; off < SCAN_BLK; off <<= 1) {
        int v = (tid >= off) ? s[tid - off] : 0;
        __syncthreads();
        s[tid] += v;
        __syncthreads();
    }
    if (i < N_NODES) {
        int ex = g_bsum[blockIdx.x] + s[tid] - c;    // exclusive prefix
        g_offs[i] = ex;
        g_cnt[i]  = ex;                               // cursor for csr_scatter
    }
    if (i == N_NODES - 1 || (i == blockIdx.x * SCAN_BLK && blockIdx.x == NBLK - 1)) {
        // last real element sets the sentinel
    }
    if (blockIdx.x == 0 && tid == 0) g_offs[N_NODES] = E_EDGES;
}

// ---------------- kernel 4: scatter src ids into CSR buckets ---------------
__global__ void csr_scatter(const int* __restrict__ src, const int* __restrict__ dst) {
    int i = blockIdx.x * blockDim.x + threadIdx.x;
    if (i >= E_EDGES) return;
    int d = dst[i];
    int p = atomicAdd(&g_cnt[d], 1);
    g_csrc[p] = src[i];
}

// ---------------- kernel 5: fused gather + softmax + bias + ELU + pool -----
__global__ void gat_gather(const int* __restrict__ batch,
                           const float* __restrict__ conv_bias) {
    const int lane = threadIdx.x & 31;
    const int d = blockIdx.x * 8 + (threadIdx.x >> 5);
    if (d >= N_NODES) return;
    const int head = lane >> 3;

    const int o0 = g_offs[d], o1 = g_offs[d + 1];
    const float2 ead = g_ead[d * H_HEADS + head];

    float4 acc = make_float4(0.f, 0.f, 0.f, 0.f);
    float densum = 0.f;

    int base = o0;
    for (; base + 32 <= o1; base += 32) {
        int eid = g_csrc[base + lane];
#pragma unroll 8
        for (int j = 0; j < 32; ++j) {
            int s = __shfl_sync(0xffffffffu, eid, j);
            float2 ef = __ldg(&g_eas[s * H_HEADS + head]);
            float p = ef.x * ead.x;
            float w = (p > 1.f) ? p : ef.y * ead.y;
            float4 hv = __ldg(&((const float4*)g_h)[(size_t)s * (HC / 4) + lane]);
            acc.x += w * hv.x; acc.y += w * hv.y;
            acc.z += w * hv.z; acc.w += w * hv.w;
            densum += w;
        }
    }
    int rem = o1 - base;
    if (rem > 0) {
        int eid = (lane < rem) ? g_csrc[base + lane] : 0;
        for (int j = 0; j < rem; ++j) {
            int s = __shfl_sync(0xffffffffu, eid, j);
            float2 ef = __ldg(&g_eas[s * H_HEADS + head]);
            float p = ef.x * ead.x;
            float w = (p > 1.f) ? p : ef.y * ead.y;
            float4 hv = __ldg(&((const float4*)g_h)[(size_t)s * (HC / 4) + lane]);
            acc.x += w * hv.x; acc.y += w * hv.y;
            acc.z += w * hv.z; acc.w += w * hv.w;
            densum += w;
        }
    }

    float inv = (densum > 0.f) ? 1.f / densum : 0.f;
    float4 bv = __ldg(&((const float4*)conv_bias)[lane]);
    float vx = acc.x * inv + bv.x; vx = vx > 0.f ? vx : __expf(vx) - 1.f;
    float vy = acc.y * inv + bv.y; vy = vy > 0.f ? vy : __expf(vy) - 1.f;
    float vz = acc.z * inv + bv.z; vz = vz > 0.f ? vz : __expf(vz) - 1.f;
    float vw = acc.w * inv + bv.w; vw = vw > 0.f ? vw : __expf(vw) - 1.f;

    int g = batch[d];
    red_add_v4(&g_pool[g * HC + lane * 4], vx, vy, vz, vw);
}

// ---------------- kernel 6: classifier + log_softmax -----------------------
__global__ void classify(const int* __restrict__ batch,
                         const float* __restrict__ lin_w,
                         const float* __restrict__ lin_b,
                         float* __restrict__ out) {
    int g = blockIdx.x, t = threadIdx.x;
    __shared__ float p[HC];
    __shared__ float logits[NCLS];
    __shared__ int s_cnt;
    if (t == 0) {
        int lo = 0, hi = N_NODES;
        while (lo < hi) { int mid = (lo + hi) >> 1; if (batch[mid] <  g) lo = mid + 1; else hi = mid; }
        int lb = lo;
        lo = lb; hi = N_NODES;
        while (lo < hi) { int mid = (lo + hi) >> 1; if (batch[mid] <= g) lo = mid + 1; else hi = mid; }
        s_cnt = lo - lb;
    }
    __syncthreads();
    float cnt = fmaxf((float)s_cnt, 1.0f);
    p[t] = g_pool[g * HC + t] / cnt;
    __syncthreads();
    if (t < NCLS) {
        float acc = lin_b[t];
#pragma unroll 16
        for (int c = 0; c < HC; ++c) acc += p[c] * lin_w[c * NCLS + t];
        logits[t] = acc;
    }
    __syncthreads();
    if (t < NCLS) {
        float m = logits[0];
#pragma unroll
        for (int j = 1; j < NCLS; ++j) m = fmaxf(m, logits[j]);
        float ssum = 0.f;
#pragma unroll
        for (int j = 0; j < NCLS; ++j) ssum += __expf(logits[j] - m);
        out[g * NCLS + t] = logits[t] - m - logf(ssum);
    }
}

// ---------------- launch ----------------------------------------------------
extern "C" void kernel_launch(void* const* d_in, const int* in_sizes, int n_in,
                              void* d_out, int out_size) {
    const float* x        = (const float*)d_in[0];
    const int*   ei       = (const int*)d_in[1];     // int32 (JAX truncates int64)
    const int*   batch    = (const int*)d_in[2];
    const float* W        = (const float*)d_in[3];
    const float* att_src  = (const float*)d_in[4];
    const float* att_dst  = (const float*)d_in[5];
    const float* conv_b   = (const float*)d_in[6];
    const float* lin_w    = (const float*)d_in[7];
    const float* lin_b    = (const float*)d_in[8];
    float*       out      = (float*)d_out;

    const int* src = ei;
    const int* dst = ei + E_EDGES;

    zero_scratch<<<(N_NODES / 4 + 255) / 256, 256>>>();
    gemm_gat<<<(N_NODES + 63) / 64, 256>>>(x, W, att_src, att_dst);
    hist_kernel<<<(E_EDGES / 4 + 255) / 256, 256>>>(dst);
    scan_blocksum<<<NBLK, SCAN_BLK>>>();
    scan_tops<<<1, 512>>>();
    scan_finalize<<<NBLK, SCAN_BLK>>>();
    csr_scatter<<<(E_EDGES + 255) / 256, 256>>>(src, dst);
    gat_gather<<<(N_NODES + 7) / 8, 256>>>(batch, conv_b);
    classify<<<G_GRAPHS, 128>>>(batch, lin_w, lin_b, out);
}